// round 1
// baseline (speedup 1.0000x reference)
#include <cuda_runtime.h>
#include <cuda_bf16.h>
#include <cstdint>

// Problem constants
#define BATCH 8
#define MDIM 2048          // L == S == 2048
#define MAUG 2049          // M+1 rows/cols (augmented)
#define STRIDE 2052        // MAUG padded to multiple of 4 for float4 alignment
#define CDIM 256
#define NITERS 20

#define NEGBIG (-1.0e30f)
#define LOGMU_MAIN (-8.317766166719343f)   // norm = -log(4096)
#define LOGMU_TAIL (-0.6931471805599453f)  // log(2048) - log(4096) = -log 2
#define MINUS_NORM (8.317766166719343f)    // -norm

// Scratch (device globals — no cudaMalloc allowed)
__device__ float g_Z [(size_t)BATCH * MAUG * STRIDE];  // augmented scores, padded rows
__device__ float g_ZT[(size_t)BATCH * MAUG * STRIDE];  // transpose, padded rows
__device__ float g_u [BATCH * STRIDE];
__device__ float g_v [BATCH * STRIDE];

// ---------------- packed f32x2 helpers ----------------
__device__ __forceinline__ unsigned long long pk2(float lo, float hi) {
    unsigned long long r;
    asm("mov.b64 %0, {%1, %2};" : "=l"(r) : "f"(lo), "f"(hi));
    return r;
}
__device__ __forceinline__ void fma2(unsigned long long& acc, unsigned long long a, unsigned long long b) {
    asm("fma.rn.f32x2 %0, %1, %2, %0;" : "+l"(acc) : "l"(a), "l"(b));
}
__device__ __forceinline__ float2 unpk(unsigned long long p) {
    float2 f;
    asm("mov.b64 {%0, %1}, %2;" : "=f"(f.x), "=f"(f.y) : "l"(p));
    return f;
}

// ---------------- GEMM: scores[b] = A[b] @ B[b]^T  (NT, K=256 contiguous) ----------------
// 128x128 tile, 256 threads, 8x8 per thread, packed f32x2 FMA.
__global__ __launch_bounds__(256, 2) void gemm_kernel(const float* __restrict__ A,
                                                      const float* __restrict__ Bm) {
    const int b = blockIdx.z;
    const float* Ab = A  + (size_t)b * MDIM * CDIM;
    const float* Bb = Bm + (size_t)b * MDIM * CDIM;
    float* Cb = g_Z + (size_t)b * MAUG * STRIDE;
    const int bm = blockIdx.y * 128, bn = blockIdx.x * 128;

    __shared__ float As[16][132];
    __shared__ float Bs[16][132];

    const int tid = threadIdx.x;
    const int tx = tid & 15, ty = tid >> 4;

    unsigned long long acc[8][4];
#pragma unroll
    for (int i = 0; i < 8; i++)
#pragma unroll
        for (int j = 0; j < 4; j++) acc[i][j] = 0ull;

    for (int k0 = 0; k0 < CDIM; k0 += 16) {
#pragma unroll
        for (int l = 0; l < 2; l++) {
            int idx = tid + l * 256;          // 0..511
            int r = idx >> 2, q = idx & 3;    // row in tile, float4 within BK=16
            float4 va = *(const float4*)(Ab + (size_t)(bm + r) * CDIM + k0 + q * 4);
            As[q * 4 + 0][r] = va.x; As[q * 4 + 1][r] = va.y;
            As[q * 4 + 2][r] = va.z; As[q * 4 + 3][r] = va.w;
            float4 vb = *(const float4*)(Bb + (size_t)(bn + r) * CDIM + k0 + q * 4);
            Bs[q * 4 + 0][r] = vb.x; Bs[q * 4 + 1][r] = vb.y;
            Bs[q * 4 + 2][r] = vb.z; Bs[q * 4 + 3][r] = vb.w;
        }
        __syncthreads();
#pragma unroll
        for (int k = 0; k < 16; k++) {
            float4 a0 = *(const float4*)&As[k][ty * 8];
            float4 a1 = *(const float4*)&As[k][ty * 8 + 4];
            float4 b0 = *(const float4*)&Bs[k][tx * 8];
            float4 b1 = *(const float4*)&Bs[k][tx * 8 + 4];
            unsigned long long pb[4] = { pk2(b0.x, b0.y), pk2(b0.z, b0.w),
                                         pk2(b1.x, b1.y), pk2(b1.z, b1.w) };
            float av[8] = { a0.x, a0.y, a0.z, a0.w, a1.x, a1.y, a1.z, a1.w };
#pragma unroll
            for (int i = 0; i < 8; i++) {
                unsigned long long pa = pk2(av[i], av[i]);
#pragma unroll
                for (int j = 0; j < 4; j++) fma2(acc[i][j], pa, pb[j]);
            }
        }
        __syncthreads();
    }
#pragma unroll
    for (int i = 0; i < 8; i++) {
        float* cp = Cb + (size_t)(bm + ty * 8 + i) * STRIDE + bn + tx * 8;
#pragma unroll
        for (int j = 0; j < 4; j++) {
            float2 f = unpk(acc[i][j]);
            *(float2*)(cp + 2 * j) = f;   // 8B aligned: row base & col offset even
        }
    }
}

// ---------------- fill dustbins, pads, init u/v ----------------
__global__ void fill_kernel(const float* __restrict__ binp) {
    const int b = blockIdx.y;
    const int t = blockIdx.x * blockDim.x + threadIdx.x;
    if (t >= MAUG) return;
    const float bin = *binp;
    float* Zb = g_Z  + (size_t)b * MAUG * STRIDE;
    float* Tb = g_ZT + (size_t)b * MAUG * STRIDE;
    Zb[(size_t)MDIM * STRIDE + t] = bin;                 // dustbin row (incl. corner)
    if (t < MDIM) Zb[(size_t)t * STRIDE + MDIM] = bin;   // dustbin col
#pragma unroll
    for (int p = MAUG; p < STRIDE; p++) {                // padding cells -> -inf-ish
        Zb[(size_t)t * STRIDE + p] = NEGBIG;
        Tb[(size_t)t * STRIDE + p] = NEGBIG;
    }
    g_v[b * STRIDE + t] = 0.0f;                          // v0 = 0
    if (t < STRIDE - MAUG) {                             // u/v pads
        g_u[b * STRIDE + MAUG + t] = NEGBIG;
        g_v[b * STRIDE + MAUG + t] = NEGBIG;
    }
}

// ---------------- tiled transpose Z -> ZT (both padded-stride) ----------------
__global__ void transpose_kernel() {
    __shared__ float t[32][33];
    const int b = blockIdx.z;
    const float* Zb = g_Z  + (size_t)b * MAUG * STRIDE;
    float* Tb       = g_ZT + (size_t)b * MAUG * STRIDE;
    int x = blockIdx.x * 32 + threadIdx.x;
    int y0 = blockIdx.y * 32;
#pragma unroll
    for (int dy = 0; dy < 32; dy += 8) {
        int y = y0 + dy + threadIdx.y;
        if (x < MAUG && y < MAUG)
            t[dy + threadIdx.y][threadIdx.x] = Zb[(size_t)y * STRIDE + x];
    }
    __syncthreads();
    int xt = blockIdx.y * 32 + threadIdx.x;
    int yt0 = blockIdx.x * 32;
#pragma unroll
    for (int dy = 0; dy < 32; dy += 8) {
        int yt = yt0 + dy + threadIdx.y;
        if (xt < MAUG && yt < MAUG)
            Tb[(size_t)yt * STRIDE + xt] = t[threadIdx.x][dy + threadIdx.y];
    }
}

// ---------------- one Sinkhorn half-iteration ----------------
// dir=0: u[b,i] = log_mu(i) - lse_j( Z[b,i,j] + v[b,j] )
// dir=1: v[b,j] = log_nu(j) - lse_i( ZT[b,j,i] + u[b,i] )   (log_mu == log_nu since m==n)
__global__ __launch_bounds__(256) void sinkhorn_half(int dir) {
    const int b = blockIdx.y, i = blockIdx.x;
    const float* Zp  = dir ? g_ZT : g_Z;
    const float* vin = dir ? g_u : g_v;
    float* uout      = dir ? g_v : g_u;

    const float4* row = (const float4*)(Zp + ((size_t)b * MAUG + i) * STRIDE);
    const float4* vv  = (const float4*)(vin + b * STRIDE);

    __shared__ float4 sx[STRIDE / 4];   // 513 float4s
    __shared__ float red[8];
    __shared__ float bcast;

    const int tid = threadIdx.x;
    float m = -3.0e38f;
    for (int j = tid; j < STRIDE / 4; j += 256) {
        float4 r = row[j];
        float4 w = vv[j];
        float4 x = { r.x + w.x, r.y + w.y, r.z + w.z, r.w + w.w };
        sx[j] = x;
        m = fmaxf(fmaxf(fmaxf(m, x.x), x.y), fmaxf(x.z, x.w));
    }
#pragma unroll
    for (int o = 16; o > 0; o >>= 1) m = fmaxf(m, __shfl_xor_sync(0xffffffffu, m, o));
    if ((tid & 31) == 0) red[tid >> 5] = m;
    __syncthreads();
    if (tid == 0) {
        float M = red[0];
#pragma unroll
        for (int w = 1; w < 8; w++) M = fmaxf(M, red[w]);
        bcast = M;
    }
    __syncthreads();
    const float M = bcast;

    float s = 0.0f;
    for (int j = tid; j < STRIDE / 4; j += 256) {
        float4 x = sx[j];
        s += __expf(x.x - M) + __expf(x.y - M) + __expf(x.z - M) + __expf(x.w - M);
    }
#pragma unroll
    for (int o = 16; o > 0; o >>= 1) s += __shfl_xor_sync(0xffffffffu, s, o);
    if ((tid & 31) == 0) red[tid >> 5] = s;
    __syncthreads();
    if (tid == 0) {
        float S = 0.0f;
#pragma unroll
        for (int w = 0; w < 8; w++) S += red[w];
        float lse = M + logf(S);
        uout[b * STRIDE + i] = ((i == MDIM) ? LOGMU_TAIL : LOGMU_MAIN) - lse;
    }
}

// ---------------- epilogue: out = Z + u + v - norm ----------------
__global__ void final_kernel(float* __restrict__ out) {
    const int b = blockIdx.z, i = blockIdx.y;
    const int j = blockIdx.x * 256 + threadIdx.x;
    if (j >= MAUG) return;
    float z = g_Z[((size_t)b * MAUG + i) * STRIDE + j];
    float u = g_u[b * STRIDE + i];
    float v = g_v[b * STRIDE + j];
    out[((size_t)b * MAUG + i) * MAUG + j] = z + u + v + MINUS_NORM;
}

// ---------------- launch ----------------
extern "C" void kernel_launch(void* const* d_in, const int* in_sizes, int n_in,
                              void* d_out, int out_size) {
    const float* f0  = (const float*)d_in[0];  // feat_c0 [8,2048,256]
    const float* f1  = (const float*)d_in[1];  // feat_c1 [8,2048,256]
    const float* bin = (const float*)d_in[2];  // bin_score scalar
    float* out = (float*)d_out;                // [8,2049,2049] fp32

    gemm_kernel<<<dim3(16, 16, BATCH), 256>>>(f0, f1);
    fill_kernel<<<dim3((MAUG + 255) / 256, BATCH), 256>>>(bin);
    transpose_kernel<<<dim3(65, 65, BATCH), dim3(32, 8)>>>();
    for (int it = 0; it < NITERS; ++it) {
        sinkhorn_half<<<dim3(MAUG, BATCH), 256>>>(0);  // update u
        sinkhorn_half<<<dim3(MAUG, BATCH), 256>>>(1);  // update v
    }
    final_kernel<<<dim3((MAUG + 255) / 256, MAUG, BATCH), 256>>>(out);
}

// round 3
// speedup vs baseline: 1.2401x; 1.2401x over previous
#include <cuda_runtime.h>
#include <cuda_fp16.h>
#include <cstdint>

// Problem constants
#define BATCH 8
#define MDIM 2048          // L == S == 2048
#define MAUG 2049          // M+1 rows/cols (augmented)
#define STRIDE 2052        // fp32 row stride (float4 aligned)
#define HSTRIDE 2056       // fp16 row stride (8-half aligned; 4112 B = 257*16)
#define CDIM 256
#define NITERS 20

#define NEGBIG (-1.0e30f)
#define HNEG (-65504.0f)
#define LOGMU_MAIN (-8.317766166719343f)   // norm = -log(4096)
#define LOGMU_TAIL (-0.6931471805599453f)  // log(2048) - log(4096) = -log 2
#define MINUS_NORM (8.317766166719343f)    // -norm

// Scratch (device globals — no cudaMalloc allowed)
__device__ float  g_Z [(size_t)BATCH * MAUG * STRIDE];   // fp32 master (epilogue)
__device__ __half g_Zh [(size_t)BATCH * MAUG * HSTRIDE]; // fp16 for sinkhorn (row LSE)
__device__ __half g_ZTh[(size_t)BATCH * MAUG * HSTRIDE]; // fp16 transpose (col LSE)
__device__ float  g_u [BATCH * HSTRIDE];
__device__ float  g_v [BATCH * HSTRIDE];

// ---------------- packed f32x2 helpers ----------------
__device__ __forceinline__ unsigned long long pk2(float lo, float hi) {
    unsigned long long r;
    asm("mov.b64 %0, {%1, %2};" : "=l"(r) : "f"(lo), "f"(hi));
    return r;
}
__device__ __forceinline__ void fma2(unsigned long long& acc, unsigned long long a, unsigned long long b) {
    asm("fma.rn.f32x2 %0, %1, %2, %0;" : "+l"(acc) : "l"(a), "l"(b));
}
__device__ __forceinline__ float2 unpk(unsigned long long p) {
    float2 f;
    asm("mov.b64 {%0, %1}, %2;" : "=f"(f.x), "=f"(f.y) : "l"(p));
    return f;
}

// ---------------- GEMM: scores[b] = A[b] @ B[b]^T (writes fp32 Z + fp16 Zh) ----------------
__global__ __launch_bounds__(256, 2) void gemm_kernel(const float* __restrict__ A,
                                                      const float* __restrict__ Bm) {
    const int b = blockIdx.z;
    const float* Ab = A  + (size_t)b * MDIM * CDIM;
    const float* Bb = Bm + (size_t)b * MDIM * CDIM;
    float* Cb = g_Z + (size_t)b * MAUG * STRIDE;
    __half* Hb = g_Zh + (size_t)b * MAUG * HSTRIDE;
    const int bm = blockIdx.y * 128, bn = blockIdx.x * 128;

    __shared__ float As[16][132];
    __shared__ float Bs[16][132];

    const int tid = threadIdx.x;
    const int tx = tid & 15, ty = tid >> 4;

    unsigned long long acc[8][4];
#pragma unroll
    for (int i = 0; i < 8; i++)
#pragma unroll
        for (int j = 0; j < 4; j++) acc[i][j] = 0ull;

    for (int k0 = 0; k0 < CDIM; k0 += 16) {
#pragma unroll
        for (int l = 0; l < 2; l++) {
            int idx = tid + l * 256;
            int r = idx >> 2, q = idx & 3;
            float4 va = *(const float4*)(Ab + (size_t)(bm + r) * CDIM + k0 + q * 4);
            As[q * 4 + 0][r] = va.x; As[q * 4 + 1][r] = va.y;
            As[q * 4 + 2][r] = va.z; As[q * 4 + 3][r] = va.w;
            float4 vb = *(const float4*)(Bb + (size_t)(bn + r) * CDIM + k0 + q * 4);
            Bs[q * 4 + 0][r] = vb.x; Bs[q * 4 + 1][r] = vb.y;
            Bs[q * 4 + 2][r] = vb.z; Bs[q * 4 + 3][r] = vb.w;
        }
        __syncthreads();
#pragma unroll
        for (int k = 0; k < 16; k++) {
            float4 a0 = *(const float4*)&As[k][ty * 8];
            float4 a1 = *(const float4*)&As[k][ty * 8 + 4];
            float4 b0 = *(const float4*)&Bs[k][tx * 8];
            float4 b1 = *(const float4*)&Bs[k][tx * 8 + 4];
            unsigned long long pb[4] = { pk2(b0.x, b0.y), pk2(b0.z, b0.w),
                                         pk2(b1.x, b1.y), pk2(b1.z, b1.w) };
            float av[8] = { a0.x, a0.y, a0.z, a0.w, a1.x, a1.y, a1.z, a1.w };
#pragma unroll
            for (int i = 0; i < 8; i++) {
                unsigned long long pa = pk2(av[i], av[i]);
#pragma unroll
                for (int j = 0; j < 4; j++) fma2(acc[i][j], pa, pb[j]);
            }
        }
        __syncthreads();
    }
#pragma unroll
    for (int i = 0; i < 8; i++) {
        const int row = bm + ty * 8 + i;
        float* cp = Cb + (size_t)row * STRIDE + bn + tx * 8;
        __half2* hp = (__half2*)(Hb + (size_t)row * HSTRIDE + bn + tx * 8);
#pragma unroll
        for (int j = 0; j < 4; j++) {
            float2 f = unpk(acc[i][j]);
            *(float2*)(cp + 2 * j) = f;
            hp[j] = __floats2half2_rn(f.x, f.y);
        }
    }
}

// ---------------- fill dustbins, pads, init u/v ----------------
__global__ void fill_kernel(const float* __restrict__ binp) {
    const int b = blockIdx.y;
    const int t = blockIdx.x * blockDim.x + threadIdx.x;
    if (t >= MAUG) return;
    const float bin = *binp;
    const __half hbin = __float2half_rn(bin);
    const __half hneg = __float2half_rn(HNEG);
    float*  Zb  = g_Z   + (size_t)b * MAUG * STRIDE;
    __half* Zhb = g_Zh  + (size_t)b * MAUG * HSTRIDE;
    __half* ZTb = g_ZTh + (size_t)b * MAUG * HSTRIDE;

    // fp32 master
    Zb[(size_t)MDIM * STRIDE + t] = bin;
    if (t < MDIM) Zb[(size_t)t * STRIDE + MDIM] = bin;
#pragma unroll
    for (int p = MAUG; p < STRIDE; p++) Zb[(size_t)t * STRIDE + p] = NEGBIG;

    // fp16 copies (dustbins; transpose overwrites interior consistently)
    Zhb[(size_t)MDIM * HSTRIDE + t] = hbin;
    ZTb[(size_t)MDIM * HSTRIDE + t] = hbin;
    if (t < MDIM) {
        Zhb[(size_t)t * HSTRIDE + MDIM] = hbin;
        ZTb[(size_t)t * HSTRIDE + MDIM] = hbin;
    }
#pragma unroll
    for (int p = MAUG; p < HSTRIDE; p++) {
        Zhb[(size_t)t * HSTRIDE + p] = hneg;
        ZTb[(size_t)t * HSTRIDE + p] = hneg;
    }
    g_v[b * HSTRIDE + t] = 0.0f;
    if (t < HSTRIDE - MAUG) {
        g_u[b * HSTRIDE + MAUG + t] = 0.0f;
        g_v[b * HSTRIDE + MAUG + t] = 0.0f;
    }
}

// ---------------- fp16 transpose Zh -> ZTh, 64x64 tiles ----------------
__global__ __launch_bounds__(256) void transpose_kernel() {
    __shared__ __half ts[64][66];
    const int b = blockIdx.z;
    const __half* Zhb = g_Zh  + (size_t)b * MAUG * HSTRIDE;
    __half* ZTb      = g_ZTh + (size_t)b * MAUG * HSTRIDE;
    const int x0 = blockIdx.x * 64, y0 = blockIdx.y * 64;
    const int tx = threadIdx.x, ty = threadIdx.y;

#pragma unroll
    for (int p = 0; p < 8; p++) {
        const int r = p * 8 + ty;
        const int y = y0 + r, x = x0 + 2 * tx;
        __half2 h = __floats2half2_rn(HNEG, HNEG);
        if (y < MAUG && x + 2 <= HSTRIDE)
            h = *(const __half2*)(Zhb + (size_t)y * HSTRIDE + x);
        *(__half2*)&ts[r][2 * tx] = h;
    }
    __syncthreads();
#pragma unroll
    for (int p = 0; p < 8; p++) {
        const int r = p * 8 + ty;
        const int xo = x0 + r, yc = y0 + 2 * tx;
        if (xo < MAUG && yc + 2 <= HSTRIDE) {
            __half2 h = __halves2half2(ts[2 * tx][r], ts[2 * tx + 1][r]);
            *(__half2*)(ZTb + (size_t)xo * HSTRIDE + yc) = h;
        }
    }
}

// ---------------- Sinkhorn half-iteration: warp-per-row online LSE ----------------
// dir=0: u[b,i] = log_mu(i) - lse_j( Zh[b,i,j] + v[b,j] )
// dir=1: v[b,j] = log_nu(j) - lse_i( ZTh[b,j,i] + u[b,i] )
__global__ __launch_bounds__(256) void sinkhorn_half(int dir) {
    const int b = blockIdx.y;
    const __half* Zp = dir ? g_ZTh : g_Zh;
    const float* vin = dir ? g_u : g_v;
    float* uout      = dir ? g_v : g_u;

    __shared__ __align__(16) float vs[HSTRIDE];
    {
        const float4* vin4 = (const float4*)(vin + b * HSTRIDE);
        float4* vs4 = (float4*)vs;
        for (int j = threadIdx.x; j < HSTRIDE / 4; j += 256) vs4[j] = vin4[j];
    }
    __syncthreads();

    const int wid = threadIdx.x >> 5, lane = threadIdx.x & 31;
    const int i = blockIdx.x * 8 + wid;
    if (i >= MAUG) return;

    const uint2* row = (const uint2*)(Zp + ((size_t)b * MAUG + i) * HSTRIDE);
    const float4* vs4 = (const float4*)vs;

    float m = -3.0e38f, s = 0.0f;
    for (int j = lane; j < HSTRIDE / 4; j += 32) {
        uint2 q = row[j];                 // 4 halves
        float4 vv = vs4[j];
        float2 a = __half22float2(*(const __half2*)&q.x);
        float2 c = __half22float2(*(const __half2*)&q.y);
        float x0 = a.x + vv.x, x1 = a.y + vv.y;
        float x2 = c.x + vv.z, x3 = c.y + vv.w;
        float cm = fmaxf(fmaxf(x0, x1), fmaxf(x2, x3));
        if (cm > m) { s *= __expf(m - cm); m = cm; }   // rare after warmup
        s += __expf(x0 - m) + __expf(x1 - m) + __expf(x2 - m) + __expf(x3 - m);
    }
#pragma unroll
    for (int o = 16; o > 0; o >>= 1) {
        float mo = __shfl_xor_sync(0xffffffffu, m, o);
        float so = __shfl_xor_sync(0xffffffffu, s, o);
        float nm = fmaxf(m, mo);
        s = s * __expf(m - nm) + so * __expf(mo - nm);
        m = nm;
    }
    if (lane == 0)
        uout[b * HSTRIDE + i] = ((i == MDIM) ? LOGMU_TAIL : LOGMU_MAIN) - (m + __logf(s));
}

// ---------------- epilogue: out = Z(fp32) + u + v - norm ----------------
__global__ void final_kernel(float* __restrict__ out) {
    const int b = blockIdx.z, i = blockIdx.y;
    const int j = blockIdx.x * 256 + threadIdx.x;
    if (j >= MAUG) return;
    float z = g_Z[((size_t)b * MAUG + i) * STRIDE + j];
    float u = g_u[b * HSTRIDE + i];
    float v = g_v[b * HSTRIDE + j];
    out[((size_t)b * MAUG + i) * MAUG + j] = z + u + v + MINUS_NORM;
}

// ---------------- launch ----------------
extern "C" void kernel_launch(void* const* d_in, const int* in_sizes, int n_in,
                              void* d_out, int out_size) {
    const float* f0  = (const float*)d_in[0];  // feat_c0 [8,2048,256]
    const float* f1  = (const float*)d_in[1];  // feat_c1 [8,2048,256]
    const float* bin = (const float*)d_in[2];  // bin_score scalar
    float* out = (float*)d_out;                // [8,2049,2049] fp32

    gemm_kernel<<<dim3(16, 16, BATCH), 256>>>(f0, f1);
    fill_kernel<<<dim3((MAUG + 255) / 256, BATCH), 256>>>(bin);
    transpose_kernel<<<dim3(33, 33, BATCH), dim3(32, 8)>>>();
    for (int it = 0; it < NITERS; ++it) {
        sinkhorn_half<<<dim3((MAUG + 7) / 8, BATCH), 256>>>(0);  // update u
        sinkhorn_half<<<dim3((MAUG + 7) / 8, BATCH), 256>>>(1);  // update v
    }
    final_kernel<<<dim3((MAUG + 255) / 256, MAUG, BATCH), 256>>>(out);
}